// round 9
// baseline (speedup 1.0000x reference)
#include <cuda_runtime.h>
#include <cuda_fp16.h>

#define NN 50000
#define NE 1600000
#define NG 64
#define FN 32
#define FE 16
#define HD 64
#define NL 3
#define BN_EPS 1e-5f
#define SCAN_B 1024
#define SCAN_NB ((NN + SCAN_B - 1) / SCAN_B)   // 49

// ---------------- static device scratch (no allocs allowed) ----------------
__device__ float  g_h[(size_t)NN * HD];         // embed output (layer-0 input)
__device__ float  g_za[(size_t)NN * HD];        // z2 ping
__device__ float  g_zb[(size_t)NN * HD];        // z2 pong
__device__ __half g_e[(size_t)NE * HD];         // edge embeddings (fp16), CSR order
__device__ int    g_src[NE];                    // src node per CSR slot
__device__ int    g_rowptr[NN + 1];
__device__ int    g_cnt[NN];                    // histogram, then cursor
__device__ int    g_bsum[SCAN_NB];
__device__ int    g_boff[SCAN_NB];
__device__ float  g_part[148 * 128];            // BN partial sums
__device__ float  g_mu[HD], g_inv[HD];
__device__ int    g_is64;                       // index dtype flag

__device__ __forceinline__ int load_idx(const void* p, long long i, int is64) {
    if (is64) return (int)((const long long*)p)[i];
    return ((const int*)p)[i];
}

__device__ __forceinline__ const float* buf_sel(int s) {
    return (s == 0) ? g_h : (s == 1) ? g_za : g_zb;
}
__device__ __forceinline__ float* buf_sel_w(int s) {
    return (s == 1) ? g_za : g_zb;
}

// Detect whether ei is int64 (all odd int32 slots == 0) or int32.
__global__ void probe_k(const int* __restrict__ ei32) {
    if (threadIdx.x != 0 || blockIdx.x != 0) return;
    int all0 = 1;
    for (int k = 0; k < 256; k++) {
        long long slot = 1 + 2LL * ((long long)k * 6247);
        if (slot < 2LL * NE && ei32[slot] != 0) { all0 = 0; break; }
    }
    g_is64 = all0;
}

__global__ void zero_cnt_k() {
    int i = blockIdx.x * blockDim.x + threadIdx.x;
    if (i < NN) g_cnt[i] = 0;
}

// h = x @ node_W + node_b   (warp per row, lane owns 2 cols)
__global__ void node_embed_k(const float* __restrict__ x,
                             const float* __restrict__ W,
                             const float* __restrict__ b) {
    int r = (blockIdx.x * blockDim.x + threadIdx.x) >> 5;
    int lane = threadIdx.x & 31;
    if (r >= NN) return;
    float2 acc = make_float2(b[2 * lane], b[2 * lane + 1]);
    const float* xr = x + (size_t)r * FN;
#pragma unroll
    for (int k = 0; k < FN; k++) {
        float xv = __ldg(xr + k);
        float2 wv = *(const float2*)(W + k * HD + 2 * lane);
        acc.x += xv * wv.x;
        acc.y += xv * wv.y;
    }
    *(float2*)(g_h + (size_t)r * HD + 2 * lane) = acc;
}

__global__ void hist_k(const void* __restrict__ ei) {
    int is64 = g_is64;
    for (long long i = blockIdx.x * blockDim.x + threadIdx.x; i < NE;
         i += (long long)gridDim.x * blockDim.x)
        atomicAdd(&g_cnt[load_idx(ei, NE + i, is64)], 1);
}

// ---- 3-kernel coalesced exclusive scan of g_cnt -> g_rowptr (+cursor) ----
__global__ void scan_partial_k() {
    int i = blockIdx.x * SCAN_B + threadIdx.x;
    int v = (i < NN) ? g_cnt[i] : 0;
    int lane = threadIdx.x & 31, w = threadIdx.x >> 5;
#pragma unroll
    for (int off = 16; off; off >>= 1) v += __shfl_down_sync(0xffffffffu, v, off);
    __shared__ int ws[32];
    if (lane == 0) ws[w] = v;
    __syncthreads();
    if (w == 0) {
        int t = ws[lane];
#pragma unroll
        for (int off = 16; off; off >>= 1) t += __shfl_down_sync(0xffffffffu, t, off);
        if (lane == 0) g_bsum[blockIdx.x] = t;
    }
}

__global__ void scan_tops_k() {
    if (threadIdx.x != 0) return;
    int run = 0;
    for (int b = 0; b < SCAN_NB; b++) {
        g_boff[b] = run;
        run += g_bsum[b];
    }
    g_rowptr[NN] = run;
}

__global__ void scan_final_k() {
    int i = blockIdx.x * SCAN_B + threadIdx.x;
    int v = (i < NN) ? g_cnt[i] : 0;
    int lane = threadIdx.x & 31, w = threadIdx.x >> 5;
    int inc = v;
#pragma unroll
    for (int off = 1; off < 32; off <<= 1) {
        int n = __shfl_up_sync(0xffffffffu, inc, off);
        if (lane >= off) inc += n;
    }
    __shared__ int ws[32];
    if (lane == 31) ws[w] = inc;
    __syncthreads();
    if (w == 0) {
        int t = ws[lane];
        int e = t;
#pragma unroll
        for (int off = 1; off < 32; off <<= 1) {
            int n = __shfl_up_sync(0xffffffffu, e, off);
            if (lane >= off) e += n;
        }
        ws[lane] = e - t;  // exclusive warp offset
    }
    __syncthreads();
    int excl = g_boff[blockIdx.x] + ws[w] + inc - v;
    if (i < NN) { g_rowptr[i] = excl; g_cnt[i] = excl; }
}

// e = edge_attr @ edge_W + edge_b (fp16), written into CSR slot; record src
__global__ void edge_build_k(const void* __restrict__ ei,
                             const float* __restrict__ ea,
                             const float* __restrict__ W,
                             const float* __restrict__ b) {
    long long e = (long long)(blockIdx.x * blockDim.x + threadIdx.x) >> 5;
    int lane = threadIdx.x & 31;
    if (e >= NE) return;
    int pos = 0;
    if (lane == 0) {
        int is64 = g_is64;
        int dst = load_idx(ei, NE + e, is64);
        pos = atomicAdd(&g_cnt[dst], 1);
        g_src[pos] = load_idx(ei, e, is64);
    }
    pos = __shfl_sync(0xffffffffu, pos, 0);
    float2 acc = make_float2(b[2 * lane], b[2 * lane + 1]);
    const float* er = ea + (size_t)e * FE;
#pragma unroll
    for (int k = 0; k < FE; k++) {
        float v = __ldg(er + k);
        float2 wv = *(const float2*)(W + k * HD + 2 * lane);
        acc.x += v * wv.x;
        acc.y += v * wv.y;
    }
    ((__half2*)g_e)[(size_t)pos * 32 + lane] = __float22half2_rn(acc);
}

// ---- fused: (BN-relu from prev layer on the fly) gather-agg + GINE MLP ----
// srcsel: 0 -> g_h (no BN), 1/2 -> g_za/g_zb with BN(a,b).
// dstsel: 1/2 -> writes raw MLP output (pre-BN) to g_za/g_zb.
__global__ __launch_bounds__(512) void fused_layer_k(
    int srcsel, int dstsel, int use_bn,
    const float* __restrict__ gamma, const float* __restrict__ beta,
    const float* __restrict__ W1, const float* __restrict__ b1,
    const float* __restrict__ W2, const float* __restrict__ b2) {
    __shared__ __align__(16) float sW1[HD * 2 * HD];  // 32KB
    __shared__ float sb1[128];
    __shared__ float sb2[64];
    __shared__ __align__(16) float zb[16][64];
    __shared__ __align__(16) float hb[16][128];
    int tid = threadIdx.x;
    for (int i = tid; i < HD * 2 * HD; i += 512) sW1[i] = W1[i];
    if (tid < 128) sb1[tid] = b1[tid];
    else if (tid < 192) sb2[tid - 128] = b2[tid - 128];
    __syncthreads();

    int w = tid >> 5, lane = tid & 31;
    int r = blockIdx.x * 16 + w;
    if (r >= NN) return;

    const float* srcb = buf_sel(srcsel);
    float* dstb = buf_sel_w(dstsel);

    // per-lane BN fold: h = relu(A*z + B)
    float2 A = make_float2(1.f, 1.f), B = make_float2(0.f, 0.f);
    if (use_bn) {
        float i0 = g_inv[2 * lane], i1 = g_inv[2 * lane + 1];
        A.x = gamma[2 * lane] * i0;
        A.y = gamma[2 * lane + 1] * i1;
        B.x = beta[2 * lane] - g_mu[2 * lane] * A.x;
        B.y = beta[2 * lane + 1] - g_mu[2 * lane + 1] * A.y;
    }

    // ---- aggregation ----
    int s0 = g_rowptr[r], s1 = g_rowptr[r + 1];
    float2 acc = make_float2(0.f, 0.f);
    const __half2* ep = (const __half2*)g_e;
    for (int s = s0; s < s1; s += 32) {
        int n = min(32, s1 - s);
        int mysrc = (lane < n) ? __ldg(&g_src[s + lane]) : 0;
        if (n == 32) {
#pragma unroll 8
            for (int j = 0; j < 32; j++) {
                int sc = __shfl_sync(0xffffffffu, mysrc, j);
                float2 ev = __half22float2(ep[(size_t)(s + j) * 32 + lane]);
                float2 hs = *(const float2*)(srcb + (size_t)sc * HD + 2 * lane);
                if (use_bn) {
                    hs.x = fmaxf(fmaf(A.x, hs.x, B.x), 0.f);
                    hs.y = fmaxf(fmaf(A.y, hs.y, B.y), 0.f);
                }
                acc.x += fmaxf(hs.x + ev.x, 0.f);
                acc.y += fmaxf(hs.y + ev.y, 0.f);
            }
        } else {
            for (int j = 0; j < n; j++) {
                int sc = __shfl_sync(0xffffffffu, mysrc, j);
                float2 ev = __half22float2(ep[(size_t)(s + j) * 32 + lane]);
                float2 hs = *(const float2*)(srcb + (size_t)sc * HD + 2 * lane);
                if (use_bn) {
                    hs.x = fmaxf(fmaf(A.x, hs.x, B.x), 0.f);
                    hs.y = fmaxf(fmaf(A.y, hs.y, B.y), 0.f);
                }
                acc.x += fmaxf(hs.x + ev.x, 0.f);
                acc.y += fmaxf(hs.y + ev.y, 0.f);
            }
        }
    }
    float2 hv = *(const float2*)(srcb + (size_t)r * HD + 2 * lane);
    if (use_bn) {
        hv.x = fmaxf(fmaf(A.x, hv.x, B.x), 0.f);
        hv.y = fmaxf(fmaf(A.y, hv.y, B.y), 0.f);
    }
    zb[w][2 * lane] = hv.x + acc.x;
    zb[w][2 * lane + 1] = hv.y + acc.y;
    __syncwarp();

    // ---- MLP: relu(z@W1+b1)@W2+b2 ----
    float4 a4 = *(const float4*)&sb1[4 * lane];
#pragma unroll
    for (int k = 0; k < 64; k++) {
        float zk = zb[w][k];
        float4 wv = *(const float4*)&sW1[k * 128 + 4 * lane];
        a4.x += zk * wv.x;
        a4.y += zk * wv.y;
        a4.z += zk * wv.z;
        a4.w += zk * wv.w;
    }
    a4.x = fmaxf(a4.x, 0.f);
    a4.y = fmaxf(a4.y, 0.f);
    a4.z = fmaxf(a4.z, 0.f);
    a4.w = fmaxf(a4.w, 0.f);
    *(float4*)&hb[w][4 * lane] = a4;
    __syncwarp();
    float2 o = make_float2(sb2[2 * lane], sb2[2 * lane + 1]);
#pragma unroll
    for (int m = 0; m < 128; m += 4) {
        float4 hh = *(const float4*)&hb[w][m];
        float2 w0 = *(const float2*)(W2 + (size_t)m * 64 + 2 * lane);
        float2 w1v = *(const float2*)(W2 + (size_t)(m + 1) * 64 + 2 * lane);
        float2 w2v = *(const float2*)(W2 + (size_t)(m + 2) * 64 + 2 * lane);
        float2 w3v = *(const float2*)(W2 + (size_t)(m + 3) * 64 + 2 * lane);
        o.x += hh.x * w0.x + hh.y * w1v.x + hh.z * w2v.x + hh.w * w3v.x;
        o.y += hh.x * w0.y + hh.y * w1v.y + hh.z * w2v.y + hh.w * w3v.y;
    }
    *(float2*)(dstb + (size_t)r * HD + 2 * lane) = o;
}

// BN partial sums over buffer sel: grid must be 148
__global__ void bn_stats_k(int sel) {
    const float* buf = buf_sel(sel);
    int c = threadIdx.x & 63, rg = threadIdx.x >> 6;
    float s = 0.f, s2 = 0.f;
    for (int r = blockIdx.x * 4 + rg; r < NN; r += 148 * 4) {
        float v = buf[(size_t)r * HD + c];
        s += v;
        s2 += v * v;
    }
    __shared__ float ps[256], ps2[256];
    ps[threadIdx.x] = s;
    ps2[threadIdx.x] = s2;
    __syncthreads();
    if (threadIdx.x < 128) {
        ps[threadIdx.x] += ps[threadIdx.x + 128];
        ps2[threadIdx.x] += ps2[threadIdx.x + 128];
    }
    __syncthreads();
    if (threadIdx.x < 64) {
        g_part[blockIdx.x * 128 + threadIdx.x] = ps[threadIdx.x] + ps[threadIdx.x + 64];
        g_part[blockIdx.x * 128 + 64 + threadIdx.x] = ps2[threadIdx.x] + ps2[threadIdx.x + 64];
    }
}

__global__ void bn_finalize_k() {
    int t = threadIdx.x;  // 64 threads
    float s = 0.f, s2 = 0.f;
    for (int i = 0; i < 148; i++) {
        s += g_part[i * 128 + t];
        s2 += g_part[i * 128 + 64 + t];
    }
    float mu = s / (float)NN;
    float var = s2 / (float)NN - mu * mu;
    g_mu[t] = mu;
    g_inv[t] = rsqrtf(var + BN_EPS);
}

// batch sorted -> contiguous ranges. Applies final BN+relu on the fly,
// mean-pools, and does the linear head. One block per graph.
__global__ void pool_final_k(int sel, const void* __restrict__ batch,
                             const float* __restrict__ gamma,
                             const float* __restrict__ beta,
                             const float* __restrict__ lw,
                             const float* __restrict__ lb,
                             float* __restrict__ out) {
    int g = blockIdx.x;
    int is64 = g_is64;
    const float* buf = buf_sel(sel);
    __shared__ int s_range[2];
    if (threadIdx.x == 0) {
        int lo = 0, hi = NN;
        while (lo < hi) { int mid = (lo + hi) >> 1; if (load_idx(batch, mid, is64) < g) lo = mid + 1; else hi = mid; }
        s_range[0] = lo;
        hi = NN;
        while (lo < hi) { int mid = (lo + hi) >> 1; if (load_idx(batch, mid, is64) < g + 1) lo = mid + 1; else hi = mid; }
        s_range[1] = lo;
    }
    __syncthreads();
    int start = s_range[0], end = s_range[1];
    int c = threadIdx.x & 63, rg = threadIdx.x >> 6;  // 4 row groups
    float a = gamma[c] * g_inv[c];
    float bb = beta[c] - g_mu[c] * a;
    float s = 0.f;
    for (int r = start + rg; r < end; r += 4)
        s += fmaxf(fmaf(a, buf[(size_t)r * HD + c], bb), 0.f);
    __shared__ float ps[256];
    ps[threadIdx.x] = s;
    __syncthreads();
    if (threadIdx.x < 128) ps[threadIdx.x] += ps[threadIdx.x + 128];
    __syncthreads();
    if (threadIdx.x < 64) {
        float gs = ps[threadIdx.x] + ps[threadIdx.x + 64];
        float cnt = fmaxf((float)(end - start), 1.0f);
        ps[threadIdx.x] = gs / cnt * lw[threadIdx.x];
    }
    __syncthreads();
    if (threadIdx.x < 32) {
        float t = ps[threadIdx.x] + ps[threadIdx.x + 32];
#pragma unroll
        for (int off = 16; off; off >>= 1) t += __shfl_down_sync(0xffffffffu, t, off);
        if (threadIdx.x == 0) out[g] = t + lb[0];
    }
}

// ---------------- launcher ----------------
extern "C" void kernel_launch(void* const* d_in, const int* in_sizes, int n_in,
                              void* d_out, int out_size) {
    const float* x = (const float*)d_in[0];
    const float* ea = (const float*)d_in[1];
    const void* ei = d_in[2];
    const void* batch = d_in[3];
    const float* node_W = (const float*)d_in[4];
    const float* node_b = (const float*)d_in[5];
    const float* edge_W = (const float*)d_in[6];
    const float* edge_b = (const float*)d_in[7];
    const float* W1s = (const float*)d_in[8];
    const float* b1s = (const float*)d_in[9];
    const float* W2s = (const float*)d_in[10];
    const float* b2s = (const float*)d_in[11];
    const float* gammas = (const float*)d_in[12];
    const float* betas = (const float*)d_in[13];
    const float* lin_W = (const float*)d_in[14];
    const float* lin_b = (const float*)d_in[15];
    float* out = (float*)d_out;

    probe_k<<<1, 32>>>((const int*)ei);
    zero_cnt_k<<<(NN + 255) / 256, 256>>>();
    node_embed_k<<<(NN * 32 + 255) / 256, 256>>>(x, node_W, node_b);
    hist_k<<<2048, 256>>>(ei);
    scan_partial_k<<<SCAN_NB, SCAN_B>>>();
    scan_tops_k<<<1, 32>>>();
    scan_final_k<<<SCAN_NB, SCAN_B>>>();
    edge_build_k<<<((size_t)NE * 32 + 255) / 256, 256>>>(ei, ea, edge_W, edge_b);

    // layer buffers: l0: g_h -> g_za ; l1: g_za -> g_zb ; l2: g_zb -> g_za
    int srcsel[NL] = {0, 1, 2};
    int dstsel[NL] = {1, 2, 1};
    for (int l = 0; l < NL; l++) {
        fused_layer_k<<<(NN + 15) / 16, 512>>>(
            srcsel[l], dstsel[l], (l > 0) ? 1 : 0,
            gammas + (l - 1) * 64, betas + (l - 1) * 64,   // unused when l==0
            W1s + (size_t)l * 64 * 128, b1s + (size_t)l * 128,
            W2s + (size_t)l * 128 * 64, b2s + (size_t)l * 64);
        bn_stats_k<<<148, 256>>>(dstsel[l]);
        bn_finalize_k<<<1, 64>>>();
    }

    pool_final_k<<<NG, 256>>>(1, batch, gammas + 2 * 64, betas + 2 * 64,
                              lin_W, lin_b, out);
}

// round 12
// speedup vs baseline: 1.4172x; 1.4172x over previous
#include <cuda_runtime.h>
#include <cuda_fp16.h>

#define NN 50000
#define NE 1600000
#define NG 64
#define FN 32
#define FE 16
#define HD 64
#define NL 3
#define BN_EPS 1e-5f
#define SCAN_B 1024
#define SCAN_NB ((NN + SCAN_B - 1) / SCAN_B)   // 49

typedef unsigned long long ull;

// ---------------- static device scratch (no allocs allowed) ----------------
__device__ float  g_h[(size_t)NN * HD];         // embed output (layer-0 input)
__device__ float  g_za[(size_t)NN * HD];        // z2 ping
__device__ float  g_zb[(size_t)NN * HD];        // z2 pong
__device__ float  g_zt[(size_t)NN * HD];        // agg output z
__device__ __half g_e[(size_t)NE * HD];         // edge embeddings (fp16), EDGE order
__device__ int    g_src[NE];                    // src node per CSR slot
__device__ int    g_perm[NE];                   // CSR slot -> edge id
__device__ int    g_rowptr[NN + 1];
__device__ int    g_cnt[NN];                    // histogram, then cursor
__device__ int    g_bsum[SCAN_NB];
__device__ int    g_boff[SCAN_NB];
__device__ float  g_part[148 * 128];            // BN partial sums
__device__ float  g_mu[HD], g_inv[HD];
__device__ int    g_is64;                       // index dtype flag

// ---- f32x2 packed helpers (Blackwell FFMA2) ----
__device__ __forceinline__ ull pack2(float lo, float hi) {
    ull r;
    asm("mov.b64 %0, {%1, %2};" : "=l"(r) : "f"(lo), "f"(hi));
    return r;
}
__device__ __forceinline__ void unpack2(ull v, float& lo, float& hi) {
    asm("mov.b64 {%0, %1}, %2;" : "=f"(lo), "=f"(hi) : "l"(v));
}
__device__ __forceinline__ void fma2(ull& d, ull a, ull b) {
    asm("fma.rn.f32x2 %0, %1, %2, %0;" : "+l"(d) : "l"(a), "l"(b));
}

__device__ __forceinline__ int load_idx(const void* p, long long i, int is64) {
    if (is64) return (int)((const long long*)p)[i];
    return ((const int*)p)[i];
}

__device__ __forceinline__ const float* buf_sel(int s) {
    return (s == 0) ? g_h : (s == 1) ? g_za : g_zb;
}
__device__ __forceinline__ float* buf_sel_w(int s) {
    return (s == 1) ? g_za : g_zb;
}

// Detect whether ei is int64 (all odd int32 slots == 0) or int32.
__global__ void probe_k(const int* __restrict__ ei32) {
    if (threadIdx.x != 0 || blockIdx.x != 0) return;
    int all0 = 1;
    for (int k = 0; k < 256; k++) {
        long long slot = 1 + 2LL * ((long long)k * 6247);
        if (slot < 2LL * NE && ei32[slot] != 0) { all0 = 0; break; }
    }
    g_is64 = all0;
}

__global__ void zero_cnt_k() {
    int i = blockIdx.x * blockDim.x + threadIdx.x;
    if (i < NN) g_cnt[i] = 0;
}

// h = x @ node_W + node_b   (warp per row, lane owns 2 cols)
__global__ void node_embed_k(const float* __restrict__ x,
                             const float* __restrict__ W,
                             const float* __restrict__ b) {
    int r = (blockIdx.x * blockDim.x + threadIdx.x) >> 5;
    int lane = threadIdx.x & 31;
    if (r >= NN) return;
    float2 acc = make_float2(b[2 * lane], b[2 * lane + 1]);
    const float* xr = x + (size_t)r * FN;
#pragma unroll
    for (int k = 0; k < FN; k++) {
        float xv = __ldg(xr + k);
        float2 wv = *(const float2*)(W + k * HD + 2 * lane);
        acc.x += xv * wv.x;
        acc.y += xv * wv.y;
    }
    *(float2*)(g_h + (size_t)r * HD + 2 * lane) = acc;
}

__global__ void hist_k(const void* __restrict__ ei) {
    int is64 = g_is64;
    for (long long i = blockIdx.x * blockDim.x + threadIdx.x; i < NE;
         i += (long long)gridDim.x * blockDim.x)
        atomicAdd(&g_cnt[load_idx(ei, NE + i, is64)], 1);
}

// ---- 3-kernel coalesced exclusive scan of g_cnt -> g_rowptr (+cursor) ----
__global__ void scan_partial_k() {
    int i = blockIdx.x * SCAN_B + threadIdx.x;
    int v = (i < NN) ? g_cnt[i] : 0;
    int lane = threadIdx.x & 31, w = threadIdx.x >> 5;
#pragma unroll
    for (int off = 16; off; off >>= 1) v += __shfl_down_sync(0xffffffffu, v, off);
    __shared__ int ws[32];
    if (lane == 0) ws[w] = v;
    __syncthreads();
    if (w == 0) {
        int t = ws[lane];
#pragma unroll
        for (int off = 16; off; off >>= 1) t += __shfl_down_sync(0xffffffffu, t, off);
        if (lane == 0) g_bsum[blockIdx.x] = t;
    }
}

__global__ void scan_tops_k() {
    if (threadIdx.x != 0) return;
    int run = 0;
    for (int b = 0; b < SCAN_NB; b++) {
        g_boff[b] = run;
        run += g_bsum[b];
    }
    g_rowptr[NN] = run;
}

__global__ void scan_final_k() {
    int i = blockIdx.x * SCAN_B + threadIdx.x;
    int v = (i < NN) ? g_cnt[i] : 0;
    int lane = threadIdx.x & 31, w = threadIdx.x >> 5;
    int inc = v;
#pragma unroll
    for (int off = 1; off < 32; off <<= 1) {
        int n = __shfl_up_sync(0xffffffffu, inc, off);
        if (lane >= off) inc += n;
    }
    __shared__ int ws[32];
    if (lane == 31) ws[w] = inc;
    __syncthreads();
    if (w == 0) {
        int t = ws[lane];
        int e = t;
#pragma unroll
        for (int off = 1; off < 32; off <<= 1) {
            int n = __shfl_up_sync(0xffffffffu, e, off);
            if (lane >= off) e += n;
        }
        ws[lane] = e - t;  // exclusive warp offset
    }
    __syncthreads();
    int excl = g_boff[blockIdx.x] + ws[w] + inc - v;
    if (i < NN) { g_rowptr[i] = excl; g_cnt[i] = excl; }
}

// thread per edge: assign CSR slot, record src + perm
__global__ void pos_k(const void* __restrict__ ei) {
    long long i = (long long)blockIdx.x * blockDim.x + threadIdx.x;
    if (i >= NE) return;
    int is64 = g_is64;
    int dst = load_idx(ei, NE + i, is64);
    int p = atomicAdd(&g_cnt[dst], 1);
    g_src[p] = load_idx(ei, i, is64);
    g_perm[p] = (int)i;
}

// e = edge_attr @ edge_W + edge_b (fp16), EDGE order, coalesced writes.
// Tiled GEMM: 256 edges/block, thread = 8 edges x 8 cols, f32x2 FMA.
__global__ __launch_bounds__(256) void edge_gemm_k(const float* __restrict__ ea,
                                                   const float* __restrict__ W,
                                                   const float* __restrict__ b) {
    __shared__ __align__(16) float sea[256 * 17];
    __shared__ __align__(16) float sW[16 * 64];
    __shared__ __align__(16) float sb[64];
    int tid = threadIdx.x;
    long long e0 = (long long)blockIdx.x * 256;
    // stage edge_attr tile (coalesced float4 -> padded smem)
    const float4* gea = (const float4*)(ea + e0 * FE);
    for (int i = tid; i < 1024; i += 256) {
        float4 v = gea[i];
        int e = i >> 2, k4 = (i & 3) << 2;
        float* d = &sea[e * 17 + k4];
        d[0] = v.x; d[1] = v.y; d[2] = v.z; d[3] = v.w;
    }
    for (int i = tid; i < 1024; i += 256) sW[i] = W[i];
    if (tid < 64) sb[tid] = b[tid];
    __syncthreads();

    int cg = tid & 7, eg = tid >> 3;     // 8 col-groups x 32 edge-groups
    ull acc[8][4];
#pragma unroll
    for (int p = 0; p < 4; p++) {
        ull bv = *(const ull*)&sb[cg * 8 + 2 * p];
#pragma unroll
        for (int j = 0; j < 8; j++) acc[j][p] = bv;
    }
#pragma unroll
    for (int k = 0; k < FE; k++) {
        ull w0 = *(const ull*)&sW[k * 64 + cg * 8];
        ull w1 = *(const ull*)&sW[k * 64 + cg * 8 + 2];
        ull w2 = *(const ull*)&sW[k * 64 + cg * 8 + 4];
        ull w3 = *(const ull*)&sW[k * 64 + cg * 8 + 6];
#pragma unroll
        for (int j = 0; j < 8; j++) {
            float a = sea[(eg * 8 + j) * 17 + k];
            ull a2 = pack2(a, a);
            fma2(acc[j][0], a2, w0);
            fma2(acc[j][1], a2, w1);
            fma2(acc[j][2], a2, w2);
            fma2(acc[j][3], a2, w3);
        }
    }
#pragma unroll
    for (int j = 0; j < 8; j++) {
        long long e = e0 + eg * 8 + j;
        uint4 o;
        float lo, hi;
        __half2 hh;
        unpack2(acc[j][0], lo, hi); hh = __floats2half2_rn(lo, hi); o.x = *(unsigned*)&hh;
        unpack2(acc[j][1], lo, hi); hh = __floats2half2_rn(lo, hi); o.y = *(unsigned*)&hh;
        unpack2(acc[j][2], lo, hi); hh = __floats2half2_rn(lo, hi); o.z = *(unsigned*)&hh;
        unpack2(acc[j][3], lo, hi); hh = __floats2half2_rn(lo, hi); o.w = *(unsigned*)&hh;
        *(uint4*)(g_e + (size_t)e * HD + cg * 8) = o;
    }
}

// warp per dst node: z = h + sum_in relu(h[src] + e)  (BN fold of prev layer)
__global__ void agg_k(int srcsel, int use_bn,
                      const float* __restrict__ gamma,
                      const float* __restrict__ beta) {
    int v = (blockIdx.x * blockDim.x + threadIdx.x) >> 5;
    int lane = threadIdx.x & 31;
    if (v >= NN) return;
    const float* srcb = buf_sel(srcsel);

    float2 A = make_float2(1.f, 1.f), B = make_float2(0.f, 0.f);
    if (use_bn) {
        A.x = gamma[2 * lane] * g_inv[2 * lane];
        A.y = gamma[2 * lane + 1] * g_inv[2 * lane + 1];
        B.x = beta[2 * lane] - g_mu[2 * lane] * A.x;
        B.y = beta[2 * lane + 1] - g_mu[2 * lane + 1] * A.y;
    }

    int s0 = g_rowptr[v], s1 = g_rowptr[v + 1];
    float2 acc = make_float2(0.f, 0.f);
    const __half2* ep = (const __half2*)g_e;
    for (int s = s0; s < s1; s += 32) {
        int n = min(32, s1 - s);
        int mysrc = 0, myperm = 0;
        if (lane < n) {
            mysrc = __ldg(&g_src[s + lane]);
            myperm = __ldg(&g_perm[s + lane]);
        }
        if (n == 32) {
#pragma unroll 8
            for (int j = 0; j < 32; j++) {
                int sc = __shfl_sync(0xffffffffu, mysrc, j);
                int pe = __shfl_sync(0xffffffffu, myperm, j);
                float2 ev = __half22float2(ep[(size_t)pe * 32 + lane]);
                float2 hs = *(const float2*)(srcb + (size_t)sc * HD + 2 * lane);
                if (use_bn) {
                    hs.x = fmaxf(fmaf(A.x, hs.x, B.x), 0.f);
                    hs.y = fmaxf(fmaf(A.y, hs.y, B.y), 0.f);
                }
                acc.x += fmaxf(hs.x + ev.x, 0.f);
                acc.y += fmaxf(hs.y + ev.y, 0.f);
            }
        } else {
            for (int j = 0; j < n; j++) {
                int sc = __shfl_sync(0xffffffffu, mysrc, j);
                int pe = __shfl_sync(0xffffffffu, myperm, j);
                float2 ev = __half22float2(ep[(size_t)pe * 32 + lane]);
                float2 hs = *(const float2*)(srcb + (size_t)sc * HD + 2 * lane);
                if (use_bn) {
                    hs.x = fmaxf(fmaf(A.x, hs.x, B.x), 0.f);
                    hs.y = fmaxf(fmaf(A.y, hs.y, B.y), 0.f);
                }
                acc.x += fmaxf(hs.x + ev.x, 0.f);
                acc.y += fmaxf(hs.y + ev.y, 0.f);
            }
        }
    }
    float2 hv = *(const float2*)(srcb + (size_t)v * HD + 2 * lane);
    if (use_bn) {
        hv.x = fmaxf(fmaf(A.x, hv.x, B.x), 0.f);
        hv.y = fmaxf(fmaf(A.y, hv.y, B.y), 0.f);
    }
    *(float2*)(g_zt + (size_t)v * HD + 2 * lane) =
        make_float2(hv.x + acc.x, hv.y + acc.y);
}

// GINE MLP as register-tiled GEMM pair: z2 = relu(z@W1+b1)@W2+b2
// 64 rows/block, 256 threads, f32x2 FMA, dynamic smem ~85KB.
#define SZ_OFF   0
#define SW_OFF   4352                 // 64*68
#define SH_OFF   (SW_OFF + 8192)      // + 64*128
#define SB1_OFF  (SH_OFF + 8448)      // + 64*132
#define SB2_OFF  (SB1_OFF + 128)
#define MLP_SMEM ((SB2_OFF + 64) * 4)
__global__ __launch_bounds__(256) void mlp_gemm_k(int dstsel,
                                                  const float* __restrict__ W1,
                                                  const float* __restrict__ b1,
                                                  const float* __restrict__ W2,
                                                  const float* __restrict__ b2) {
    extern __shared__ __align__(16) float sm[];
    float* sz = sm + SZ_OFF;    // [64][68]
    float* sW = sm + SW_OFF;    // [64][128] then [128][64]
    float* sh = sm + SH_OFF;    // [64][132]
    float* sb1 = sm + SB1_OFF;
    float* sb2 = sm + SB2_OFF;
    int tid = threadIdx.x;
    int r0 = blockIdx.x * 64;

    for (int i = tid; i < 1024; i += 256) {
        int r = i >> 4, c4 = (i & 15) << 2;
        float4 v = make_float4(0.f, 0.f, 0.f, 0.f);
        if (r0 + r < NN) v = *(const float4*)&g_zt[(size_t)(r0 + r) * HD + c4];
        *(float4*)&sz[r * 68 + c4] = v;
    }
    for (int i = tid; i < 8192; i += 256) sW[i] = W1[i];
    if (tid < 128) sb1[tid] = b1[tid];
    else if (tid < 192) sb2[tid - 128] = b2[tid - 128];
    __syncthreads();

    // GEMM1: 64x128 = (rg:8 rows x 8) x (cg:32 cols x 4)
    {
        int cg = tid & 31, rg = tid >> 5;
        ull acc[8][2];
        ull bb0 = *(const ull*)&sb1[cg * 4];
        ull bb1 = *(const ull*)&sb1[cg * 4 + 2];
#pragma unroll
        for (int j = 0; j < 8; j++) { acc[j][0] = bb0; acc[j][1] = bb1; }
#pragma unroll 4
        for (int k = 0; k < 64; k++) {
            ull w0 = *(const ull*)&sW[k * 128 + cg * 4];
            ull w1 = *(const ull*)&sW[k * 128 + cg * 4 + 2];
#pragma unroll
            for (int j = 0; j < 8; j++) {
                float a = sz[(rg * 8 + j) * 68 + k];
                ull a2 = pack2(a, a);
                fma2(acc[j][0], a2, w0);
                fma2(acc[j][1], a2, w1);
            }
        }
#pragma unroll
        for (int j = 0; j < 8; j++) {
            float x0, x1, x2, x3;
            unpack2(acc[j][0], x0, x1);
            unpack2(acc[j][1], x2, x3);
            float4 hv = make_float4(fmaxf(x0, 0.f), fmaxf(x1, 0.f),
                                    fmaxf(x2, 0.f), fmaxf(x3, 0.f));
            *(float4*)&sh[(rg * 8 + j) * 132 + cg * 4] = hv;
        }
    }
    __syncthreads();
    for (int i = tid; i < 8192; i += 256) sW[i] = W2[i];
    __syncthreads();

    // GEMM2: 64x64 = (rg2:16 rows x 4) x (cg2:16 cols x 4)
    {
        int cg2 = tid & 15, rg2 = tid >> 4;
        ull acc[4][2];
        ull bb0 = *(const ull*)&sb2[cg2 * 4];
        ull bb1 = *(const ull*)&sb2[cg2 * 4 + 2];
#pragma unroll
        for (int j = 0; j < 4; j++) { acc[j][0] = bb0; acc[j][1] = bb1; }
#pragma unroll 4
        for (int k = 0; k < 128; k++) {
            ull w0 = *(const ull*)&sW[k * 64 + cg2 * 4];
            ull w1 = *(const ull*)&sW[k * 64 + cg2 * 4 + 2];
#pragma unroll
            for (int j = 0; j < 4; j++) {
                float a = sh[(rg2 * 4 + j) * 132 + k];
                ull a2 = pack2(a, a);
                fma2(acc[j][0], a2, w0);
                fma2(acc[j][1], a2, w1);
            }
        }
        float* dstb = buf_sel_w(dstsel);
#pragma unroll
        for (int j = 0; j < 4; j++) {
            int r = r0 + rg2 * 4 + j;
            if (r < NN) {
                float x0, x1, x2, x3;
                unpack2(acc[j][0], x0, x1);
                unpack2(acc[j][1], x2, x3);
                *(float4*)&dstb[(size_t)r * HD + cg2 * 4] =
                    make_float4(x0, x1, x2, x3);
            }
        }
    }
}

// BN partial sums over buffer sel: grid must be 148
__global__ void bn_stats_k(int sel) {
    const float* buf = buf_sel(sel);
    int c = threadIdx.x & 63, rg = threadIdx.x >> 6;
    float s = 0.f, s2 = 0.f;
    for (int r = blockIdx.x * 4 + rg; r < NN; r += 148 * 4) {
        float v = buf[(size_t)r * HD + c];
        s += v;
        s2 += v * v;
    }
    __shared__ float ps[256], ps2[256];
    ps[threadIdx.x] = s;
    ps2[threadIdx.x] = s2;
    __syncthreads();
    if (threadIdx.x < 128) {
        ps[threadIdx.x] += ps[threadIdx.x + 128];
        ps2[threadIdx.x] += ps2[threadIdx.x + 128];
    }
    __syncthreads();
    if (threadIdx.x < 64) {
        g_part[blockIdx.x * 128 + threadIdx.x] = ps[threadIdx.x] + ps[threadIdx.x + 64];
        g_part[blockIdx.x * 128 + 64 + threadIdx.x] = ps2[threadIdx.x] + ps2[threadIdx.x + 64];
    }
}

__global__ void bn_finalize_k() {
    int t = threadIdx.x;  // 64 threads
    float s = 0.f, s2 = 0.f;
    for (int i = 0; i < 148; i++) {
        s += g_part[i * 128 + t];
        s2 += g_part[i * 128 + 64 + t];
    }
    float mu = s / (float)NN;
    float var = s2 / (float)NN - mu * mu;
    g_mu[t] = mu;
    g_inv[t] = rsqrtf(var + BN_EPS);
}

// batch sorted -> contiguous ranges; BN+relu on the fly, mean-pool, head.
__global__ void pool_final_k(int sel, const void* __restrict__ batch,
                             const float* __restrict__ gamma,
                             const float* __restrict__ beta,
                             const float* __restrict__ lw,
                             const float* __restrict__ lb,
                             float* __restrict__ out) {
    int g = blockIdx.x;
    int is64 = g_is64;
    const float* buf = buf_sel(sel);
    __shared__ int s_range[2];
    if (threadIdx.x == 0) {
        int lo = 0, hi = NN;
        while (lo < hi) { int mid = (lo + hi) >> 1; if (load_idx(batch, mid, is64) < g) lo = mid + 1; else hi = mid; }
        s_range[0] = lo;
        hi = NN;
        while (lo < hi) { int mid = (lo + hi) >> 1; if (load_idx(batch, mid, is64) < g + 1) lo = mid + 1; else hi = mid; }
        s_range[1] = lo;
    }
    __syncthreads();
    int start = s_range[0], end = s_range[1];
    int c = threadIdx.x & 63, rg = threadIdx.x >> 6;
    float a = gamma[c] * g_inv[c];
    float bb = beta[c] - g_mu[c] * a;
    float s = 0.f;
    for (int r = start + rg; r < end; r += 4)
        s += fmaxf(fmaf(a, buf[(size_t)r * HD + c], bb), 0.f);
    __shared__ float ps[256];
    ps[threadIdx.x] = s;
    __syncthreads();
    if (threadIdx.x < 128) ps[threadIdx.x] += ps[threadIdx.x + 128];
    __syncthreads();
    if (threadIdx.x < 64) {
        float gs = ps[threadIdx.x] + ps[threadIdx.x + 64];
        float cnt = fmaxf((float)(end - start), 1.0f);
        ps[threadIdx.x] = gs / cnt * lw[threadIdx.x];
    }
    __syncthreads();
    if (threadIdx.x < 32) {
        float t = ps[threadIdx.x] + ps[threadIdx.x + 32];
#pragma unroll
        for (int off = 16; off; off >>= 1) t += __shfl_down_sync(0xffffffffu, t, off);
        if (threadIdx.x == 0) out[g] = t + lb[0];
    }
}

// ---------------- launcher ----------------
extern "C" void kernel_launch(void* const* d_in, const int* in_sizes, int n_in,
                              void* d_out, int out_size) {
    const float* x = (const float*)d_in[0];
    const float* ea = (const float*)d_in[1];
    const void* ei = d_in[2];
    const void* batch = d_in[3];
    const float* node_W = (const float*)d_in[4];
    const float* node_b = (const float*)d_in[5];
    const float* edge_W = (const float*)d_in[6];
    const float* edge_b = (const float*)d_in[7];
    const float* W1s = (const float*)d_in[8];
    const float* b1s = (const float*)d_in[9];
    const float* W2s = (const float*)d_in[10];
    const float* b2s = (const float*)d_in[11];
    const float* gammas = (const float*)d_in[12];
    const float* betas = (const float*)d_in[13];
    const float* lin_W = (const float*)d_in[14];
    const float* lin_b = (const float*)d_in[15];
    float* out = (float*)d_out;

    cudaFuncSetAttribute(mlp_gemm_k, cudaFuncAttributeMaxDynamicSharedMemorySize,
                         MLP_SMEM);

    probe_k<<<1, 32>>>((const int*)ei);
    zero_cnt_k<<<(NN + 255) / 256, 256>>>();
    node_embed_k<<<(NN * 32 + 255) / 256, 256>>>(x, node_W, node_b);
    hist_k<<<2048, 256>>>(ei);
    scan_partial_k<<<SCAN_NB, SCAN_B>>>();
    scan_tops_k<<<1, 32>>>();
    scan_final_k<<<SCAN_NB, SCAN_B>>>();
    pos_k<<<(NE + 255) / 256, 256>>>(ei);
    edge_gemm_k<<<NE / 256, 256>>>(ea, edge_W, edge_b);

    // layer buffers: l0: g_h -> g_za ; l1: g_za -> g_zb ; l2: g_zb -> g_za
    int srcsel[NL] = {0, 1, 2};
    int dstsel[NL] = {1, 2, 1};
    for (int l = 0; l < NL; l++) {
        agg_k<<<(NN * 32 + 255) / 256, 256>>>(
            srcsel[l], (l > 0) ? 1 : 0,
            gammas + (l - 1) * 64, betas + (l - 1) * 64);
        mlp_gemm_k<<<(NN + 63) / 64, 256, MLP_SMEM>>>(
            dstsel[l],
            W1s + (size_t)l * 64 * 128, b1s + (size_t)l * 128,
            W2s + (size_t)l * 128 * 64, b2s + (size_t)l * 64);
        bn_stats_k<<<148, 256>>>(dstsel[l]);
        bn_finalize_k<<<1, 64>>>();
    }

    pool_final_k<<<NG, 256>>>(1, batch, gammas + 2 * 64, betas + 2 * 64,
                              lin_W, lin_b, out);
}